// round 5
// baseline (speedup 1.0000x reference)
#include <cuda_runtime.h>
#include <cstdint>

#define B_DIM 32
#define S_DIM 1024
#define H_DIM 1024
#define I_DIM 1024
#define KW    2048

__device__ float g_G[(size_t)3 * S_DIM * B_DIM * H_DIM]; // [g][t][b][h]
__device__ float g_hT[2][H_DIM * B_DIM];                 // h transposed [h][b]
__device__ unsigned g_barCount = 0;
__device__ unsigned g_barGen   = 0;

__device__ __forceinline__ unsigned long long pack2(float lo, float hi) {
    unsigned long long r;
    asm("mov.b64 %0, {%1, %2};" : "=l"(r)
        : "r"(__float_as_uint(lo)), "r"(__float_as_uint(hi)));
    return r;
}
__device__ __forceinline__ unsigned long long ffma2(unsigned long long a,
                                                    unsigned long long b,
                                                    unsigned long long c) {
    unsigned long long d;
    asm("fma.rn.f32x2 %0, %1, %2, %3;" : "=l"(d) : "l"(a), "l"(b), "l"(c));
    return d;
}
__device__ __forceinline__ float2 unpack2(unsigned long long v) {
    unsigned lo, hi;
    asm("mov.b64 {%0, %1}, %2;" : "=r"(lo), "=r"(hi) : "l"(v));
    float2 f; f.x = __uint_as_float(lo); f.y = __uint_as_float(hi);
    return f;
}

// ============ Phase 1: G = x @ W[:, :I]^T + b, 3 gates ============
__global__ __launch_bounds__(256, 2)
void lstm_gemm_x(const float* __restrict__ x,
                 const float* __restrict__ Wf, const float* __restrict__ Wo,
                 const float* __restrict__ Wc,
                 const float* __restrict__ bf, const float* __restrict__ bo,
                 const float* __restrict__ bc) {
    __shared__ float As[8][128];
    __shared__ float Bs[8][128];

    const int g = blockIdx.z;
    const float* W    = (g == 0) ? Wf : (g == 1 ? Wo : Wc);
    const float* bias = (g == 0) ? bf : (g == 1 ? bo : bc);

    const int rowBase = blockIdx.y * 128;
    const int colBase = blockIdx.x * 128;
    const int tid  = threadIdx.x;
    const int lr   = tid >> 1;
    const int lk   = (tid & 1) * 4;
    const int mIdx = tid >> 4;
    const int nIdx = tid & 15;

    const float* aPtr = x + (size_t)(rowBase + lr) * I_DIM + lk;
    const float* bPtr = W + (size_t)(colBase + lr) * KW    + lk;

    unsigned long long acc[8][4];
#pragma unroll
    for (int i = 0; i < 8; i++)
#pragma unroll
        for (int j = 0; j < 4; j++) acc[i][j] = 0ull;

    float4 av = *(const float4*)aPtr;
    float4 bv = *(const float4*)bPtr;

    for (int kt = 0; kt < 1024; kt += 8) {
        As[lk + 0][lr] = av.x; As[lk + 1][lr] = av.y;
        As[lk + 2][lr] = av.z; As[lk + 3][lr] = av.w;
        Bs[lk + 0][lr] = bv.x; Bs[lk + 1][lr] = bv.y;
        Bs[lk + 2][lr] = bv.z; Bs[lk + 3][lr] = bv.w;
        __syncthreads();

        if (kt + 8 < 1024) {
            av = *(const float4*)(aPtr + kt + 8);
            bv = *(const float4*)(bPtr + kt + 8);
        }

#pragma unroll
        for (int k = 0; k < 8; k++) {
            float4 a0 = *(const float4*)&As[k][mIdx * 4];
            float4 a1 = *(const float4*)&As[k][64 + mIdx * 4];
            longlong2 b0 = *(const longlong2*)&Bs[k][nIdx * 4];
            longlong2 b1 = *(const longlong2*)&Bs[k][64 + nIdx * 4];

            unsigned long long ad[8];
            ad[0] = pack2(a0.x, a0.x); ad[1] = pack2(a0.y, a0.y);
            ad[2] = pack2(a0.z, a0.z); ad[3] = pack2(a0.w, a0.w);
            ad[4] = pack2(a1.x, a1.x); ad[5] = pack2(a1.y, a1.y);
            ad[6] = pack2(a1.z, a1.z); ad[7] = pack2(a1.w, a1.w);

            unsigned long long bp0 = (unsigned long long)b0.x;
            unsigned long long bp1 = (unsigned long long)b0.y;
            unsigned long long bp2 = (unsigned long long)b1.x;
            unsigned long long bp3 = (unsigned long long)b1.y;
#pragma unroll
            for (int i = 0; i < 8; i++) {
                acc[i][0] = ffma2(ad[i], bp0, acc[i][0]);
                acc[i][1] = ffma2(ad[i], bp1, acc[i][1]);
                acc[i][2] = ffma2(ad[i], bp2, acc[i][2]);
                acc[i][3] = ffma2(ad[i], bp3, acc[i][3]);
            }
        }
        __syncthreads();
    }

#pragma unroll
    for (int i = 0; i < 8; i++) {
        int r  = rowBase + ((i < 4) ? (mIdx * 4 + i) : (64 + mIdx * 4 + (i - 4)));
        int bb = r >> 10;
        int ss = r & 1023;
        float* orow = g_G + (((size_t)g * S_DIM + ss) * B_DIM + bb) * H_DIM;
#pragma unroll
        for (int p = 0; p < 4; p++) {
            int cc = colBase + ((p < 2) ? (nIdx * 4 + p * 2)
                                        : (64 + nIdx * 4 + (p - 2) * 2));
            float2 v = unpack2(acc[i][p]);
            v.x += bias[cc];
            v.y += bias[cc + 1];
            *(float2*)&orow[cc] = v;
        }
    }
}

// ============ init h0 (transposed) ============
__global__ void lstm_init_h(const float* __restrict__ h0) {
    int idx = blockIdx.x * blockDim.x + threadIdx.x;
    if (idx < B_DIM * H_DIM) {
        int b = idx >> 10, h = idx & 1023;
        g_hT[0][h * B_DIM + b] = h0[idx];
    }
}

// ============ Phase 2: persistent recurrence ============
#define NB_CTA 128
#define CPB    8
#define NTH    192
#define WSTRIDE 1032
#define SMEM_BYTES ((3 * CPB * WSTRIDE + 1024 * 32 + 32 * CPB) * 4)

__device__ __forceinline__ void gridSync(unsigned nb) {
    __syncthreads();
    if (threadIdx.x == 0) {
        __threadfence();
        unsigned gen = *(volatile unsigned*)&g_barGen;
        if (atomicAdd(&g_barCount, 1u) == nb - 1u) {
            *(volatile unsigned*)&g_barCount = 0u;
            __threadfence();
            *(volatile unsigned*)&g_barGen = gen + 1u;
        } else {
            while (*(volatile unsigned*)&g_barGen == gen) { __nanosleep(32); }
        }
        __threadfence();
    }
    __syncthreads();
}

extern __shared__ float s_mem[];

__global__ __launch_bounds__(NTH, 1)
void lstm_recurrent(const float* __restrict__ Wf, const float* __restrict__ Wo,
                    const float* __restrict__ Wc, const float* __restrict__ c0,
                    float* __restrict__ out, int out_size) {
    float* ws    = s_mem;                          // 3*8*1032 floats
    float* hbuf  = s_mem + 3 * CPB * WSTRIDE;      // 32768 floats
    float* csm   = hbuf + 1024 * 32;               // 256 floats
    float* gates = hbuf;                           // alias, phase-synced

    const int tid   = threadIdx.x;
    const int c0col = blockIdx.x * CPB;
    const int q  = tid & 7;
    const int cl = (tid >> 3) & 7;
    const int g  = tid >> 6;
    const unsigned nb = gridDim.x;

    // recurrent weights -> smem: ws[g][c][k] = Wg[c0col+c][I+k]
    for (int idx = tid; idx < 3 * CPB * 256; idx += NTH) {
        int gg  = idx / (CPB * 256);
        int rem = idx - gg * (CPB * 256);
        int cc  = rem >> 8;
        int kq  = rem & 255;
        const float* Wsel = (gg == 0) ? Wf : (gg == 1 ? Wo : Wc);
        float4 v = *(const float4*)(Wsel + (size_t)(c0col + cc) * KW + I_DIM + kq * 4);
        *(float4*)&ws[(gg * CPB + cc) * WSTRIDE + kq * 4] = v;
    }
    for (int idx = tid; idx < B_DIM * CPB; idx += NTH) {
        int bb = idx >> 3, cc = idx & 7;
        csm[bb * CPB + cc] = c0[bb * H_DIM + c0col + cc];
    }
    __syncthreads();

    const float* wrow = &ws[(g * CPB + cl) * WSTRIDE];
    const bool wantTail = (out_size >= (B_DIM * S_DIM * H_DIM + 2 * B_DIM * H_DIM));

    for (int t = 0; t < S_DIM; t++) {
        const float* hsrc = g_hT[t & 1];
        float*       hdst = g_hT[(t + 1) & 1];

        for (int idx = tid; idx < 8192; idx += NTH) {
            float4 v = __ldcg(((const float4*)hsrc) + idx);
            *(float4*)&hbuf[idx * 4] = v;
        }
        __syncthreads();

        unsigned long long a01 = 0ull, a23 = 0ull;
#pragma unroll 4
        for (int kq = 0; kq < 256; kq++) {
            float4 w4 = *(const float4*)&wrow[kq * 4];
            float wj[4] = {w4.x, w4.y, w4.z, w4.w};
#pragma unroll
            for (int j = 0; j < 4; j++) {
                longlong2 hv = *(const longlong2*)&hbuf[(kq * 4 + j) * 32 + q * 4];
                unsigned long long wd = pack2(wj[j], wj[j]);
                a01 = ffma2(wd, (unsigned long long)hv.x, a01);
                a23 = ffma2(wd, (unsigned long long)hv.y, a23);
            }
        }
        float2 s01 = unpack2(a01), s23 = unpack2(a23);
        float sv[4] = {s01.x, s01.y, s23.x, s23.y};

        __syncthreads();   // all hbuf reads done before gates alias write

        const float* Gt = g_G + ((size_t)g * S_DIM + t) * (B_DIM * H_DIM);
#pragma unroll
        for (int j = 0; j < 4; j++) {
            int bb = q * 4 + j;
            float pre = sv[j] + Gt[(size_t)bb * H_DIM + c0col + cl];
            gates[(g * B_DIM + bb) * CPB + cl] = pre;
        }
        __syncthreads();

        for (int idx = tid; idx < B_DIM * CPB; idx += NTH) {
            int cc = idx & 7, bb = idx >> 3;
            float fp = gates[(0 * B_DIM + bb) * CPB + cc];
            float op = gates[(1 * B_DIM + bb) * CPB + cc];
            float cp = gates[(2 * B_DIM + bb) * CPB + cc];
            float f  = 1.f / (1.f + expf(-fp));
            float o  = 1.f / (1.f + expf(-op));
            float ch = tanhf(cp);
            float cold = csm[bb * CPB + cc];
            float cn = f * cold + (1.f - f) * ch;
            float hn = o * tanhf(cn);
            csm[bb * CPB + cc] = cn;
            int colg = c0col + cc;
            __stcg(&hdst[colg * B_DIM + bb], hn);
            out[((size_t)bb * S_DIM + t) * H_DIM + colg] = hn;
            if (t == S_DIM - 1 && wantTail) {
                size_t base = (size_t)B_DIM * S_DIM * H_DIM;
                out[base + (size_t)bb * H_DIM + colg] = hn;
                out[base + (size_t)B_DIM * H_DIM + (size_t)bb * H_DIM + colg] = cn;
            }
        }
        gridSync(nb);
    }
}

extern "C" void kernel_launch(void* const* d_in, const int* in_sizes, int n_in,
                              void* d_out, int out_size) {
    const float* x  = (const float*)d_in[0];
    const float* h0 = (const float*)d_in[1];
    const float* c0 = (const float*)d_in[2];
    const float* Wf = (const float*)d_in[3];
    const float* bf = (const float*)d_in[4];
    const float* Wo = (const float*)d_in[5];
    const float* bo = (const float*)d_in[6];
    const float* Wc = (const float*)d_in[7];
    const float* bc = (const float*)d_in[8];
    float* out = (float*)d_out;

    cudaFuncSetAttribute(lstm_recurrent,
                         cudaFuncAttributeMaxDynamicSharedMemorySize, SMEM_BYTES);

    dim3 gg(H_DIM / 128, (B_DIM * S_DIM) / 128, 3);
    lstm_gemm_x<<<gg, 256>>>(x, Wf, Wo, Wc, bf, bo, bc);
    lstm_init_h<<<(B_DIM * H_DIM + 255) / 256, 256>>>(h0);
    lstm_recurrent<<<NB_CTA, NTH, SMEM_BYTES>>>(Wf, Wo, Wc, c0, out, out_size);
}

// round 6
// speedup vs baseline: 1.2745x; 1.2745x over previous
#include <cuda_runtime.h>
#include <cstdint>

#define B_DIM 32
#define S_DIM 1024
#define H_DIM 1024
#define I_DIM 1024
#define KW    2048

__device__ float g_G[(size_t)3 * S_DIM * B_DIM * H_DIM]; // [g][t][b][h]
__device__ float g_hT[2][H_DIM * B_DIM];                 // h transposed [h][b]
__device__ unsigned g_barCount = 0;
__device__ unsigned g_barGen   = 0;

__device__ __forceinline__ unsigned long long pack2(float lo, float hi) {
    unsigned long long r;
    asm("mov.b64 %0, {%1, %2};" : "=l"(r)
        : "r"(__float_as_uint(lo)), "r"(__float_as_uint(hi)));
    return r;
}
__device__ __forceinline__ unsigned long long ffma2(unsigned long long a,
                                                    unsigned long long b,
                                                    unsigned long long c) {
    unsigned long long d;
    asm("fma.rn.f32x2 %0, %1, %2, %3;" : "=l"(d) : "l"(a), "l"(b), "l"(c));
    return d;
}
__device__ __forceinline__ float2 unpack2(unsigned long long v) {
    unsigned lo, hi;
    asm("mov.b64 {%0, %1}, %2;" : "=r"(lo), "=r"(hi) : "l"(v));
    float2 f; f.x = __uint_as_float(lo); f.y = __uint_as_float(hi);
    return f;
}

// ============ Phase 1: G = x @ W[:, :I]^T + b, 3 gates (unchanged) ============
__global__ __launch_bounds__(256, 2)
void lstm_gemm_x(const float* __restrict__ x,
                 const float* __restrict__ Wf, const float* __restrict__ Wo,
                 const float* __restrict__ Wc,
                 const float* __restrict__ bf, const float* __restrict__ bo,
                 const float* __restrict__ bc) {
    __shared__ float As[8][128];
    __shared__ float Bs[8][128];

    const int g = blockIdx.z;
    const float* W    = (g == 0) ? Wf : (g == 1 ? Wo : Wc);
    const float* bias = (g == 0) ? bf : (g == 1 ? bo : bc);

    const int rowBase = blockIdx.y * 128;
    const int colBase = blockIdx.x * 128;
    const int tid  = threadIdx.x;
    const int lr   = tid >> 1;
    const int lk   = (tid & 1) * 4;
    const int mIdx = tid >> 4;
    const int nIdx = tid & 15;

    const float* aPtr = x + (size_t)(rowBase + lr) * I_DIM + lk;
    const float* bPtr = W + (size_t)(colBase + lr) * KW    + lk;

    unsigned long long acc[8][4];
#pragma unroll
    for (int i = 0; i < 8; i++)
#pragma unroll
        for (int j = 0; j < 4; j++) acc[i][j] = 0ull;

    float4 av = *(const float4*)aPtr;
    float4 bv = *(const float4*)bPtr;

    for (int kt = 0; kt < 1024; kt += 8) {
        As[lk + 0][lr] = av.x; As[lk + 1][lr] = av.y;
        As[lk + 2][lr] = av.z; As[lk + 3][lr] = av.w;
        Bs[lk + 0][lr] = bv.x; Bs[lk + 1][lr] = bv.y;
        Bs[lk + 2][lr] = bv.z; Bs[lk + 3][lr] = bv.w;
        __syncthreads();

        if (kt + 8 < 1024) {
            av = *(const float4*)(aPtr + kt + 8);
            bv = *(const float4*)(bPtr + kt + 8);
        }

#pragma unroll
        for (int k = 0; k < 8; k++) {
            float4 a0 = *(const float4*)&As[k][mIdx * 4];
            float4 a1 = *(const float4*)&As[k][64 + mIdx * 4];
            longlong2 b0 = *(const longlong2*)&Bs[k][nIdx * 4];
            longlong2 b1 = *(const longlong2*)&Bs[k][64 + nIdx * 4];

            unsigned long long ad[8];
            ad[0] = pack2(a0.x, a0.x); ad[1] = pack2(a0.y, a0.y);
            ad[2] = pack2(a0.z, a0.z); ad[3] = pack2(a0.w, a0.w);
            ad[4] = pack2(a1.x, a1.x); ad[5] = pack2(a1.y, a1.y);
            ad[6] = pack2(a1.z, a1.z); ad[7] = pack2(a1.w, a1.w);

            unsigned long long bp0 = (unsigned long long)b0.x;
            unsigned long long bp1 = (unsigned long long)b0.y;
            unsigned long long bp2 = (unsigned long long)b1.x;
            unsigned long long bp3 = (unsigned long long)b1.y;
#pragma unroll
            for (int i = 0; i < 8; i++) {
                acc[i][0] = ffma2(ad[i], bp0, acc[i][0]);
                acc[i][1] = ffma2(ad[i], bp1, acc[i][1]);
                acc[i][2] = ffma2(ad[i], bp2, acc[i][2]);
                acc[i][3] = ffma2(ad[i], bp3, acc[i][3]);
            }
        }
        __syncthreads();
    }

#pragma unroll
    for (int i = 0; i < 8; i++) {
        int r  = rowBase + ((i < 4) ? (mIdx * 4 + i) : (64 + mIdx * 4 + (i - 4)));
        int bb = r >> 10;
        int ss = r & 1023;
        float* orow = g_G + (((size_t)g * S_DIM + ss) * B_DIM + bb) * H_DIM;
#pragma unroll
        for (int p = 0; p < 4; p++) {
            int cc = colBase + ((p < 2) ? (nIdx * 4 + p * 2)
                                        : (64 + nIdx * 4 + (p - 2) * 2));
            float2 v = unpack2(acc[i][p]);
            v.x += bias[cc];
            v.y += bias[cc + 1];
            *(float2*)&orow[cc] = v;
        }
    }
}

// ============ init h0 (transposed) ============
__global__ void lstm_init_h(const float* __restrict__ h0) {
    int idx = blockIdx.x * blockDim.x + threadIdx.x;
    if (idx < B_DIM * H_DIM) {
        int b = idx >> 10, h = idx & 1023;
        g_hT[0][h * B_DIM + b] = h0[idx];
    }
}

// ============ Phase 2: persistent recurrence (register-blocked) ============
#define NB_CTA 128
#define CPB    8
#define NTH    192
// smem: ws 24*1024 | hbuf 1024*32 (aliased by partials) | csm 256
#define SMEM_FLOATS (24 * 1024 + 32 * 1024 + 256)
#define SMEM_BYTES (SMEM_FLOATS * 4)

__device__ __forceinline__ void gridSync(unsigned nb) {
    __syncthreads();
    if (threadIdx.x == 0) {
        __threadfence();
        unsigned gen = *(volatile unsigned*)&g_barGen;
        if (atomicAdd(&g_barCount, 1u) == nb - 1u) {
            *(volatile unsigned*)&g_barCount = 0u;
            __threadfence();
            *(volatile unsigned*)&g_barGen = gen + 1u;
        } else {
            while (*(volatile unsigned*)&g_barGen == gen) { __nanosleep(32); }
        }
        __threadfence();
    }
    __syncthreads();
}

extern __shared__ float s_mem[];

__global__ __launch_bounds__(NTH, 1)
void lstm_recurrent(const float* __restrict__ Wf, const float* __restrict__ Wo,
                    const float* __restrict__ Wc, const float* __restrict__ c0,
                    float* __restrict__ out, int out_size) {
    float* ws   = s_mem;                       // 24 rows x 1024
    float* hbuf = s_mem + 24 * 1024;           // [k][32] XOR-swizzled chunks
    float* csm  = s_mem + 24 * 1024 + 32 * 1024;
    float* part = hbuf;                        // alias, phase-synced: [row][b] stride 17

    const int tid   = threadIdx.x;
    const int c0col = blockIdx.x * CPB;
    const int lane  = tid & 31;
    const int warp  = tid >> 5;          // 6 warps
    const int ks    = lane & 7;          // k-lane within warp
    const int bg    = lane >> 3;         // batch-group (8 batches)
    const int rg    = warp % 3;          // gate (8 rows)
    const int kh    = warp / 3;          // K-half
    const unsigned nb = gridDim.x;

    // recurrent weights -> smem: ws[g*8+c][k] = Wg[c0col+c][I+k]
    for (int idx = tid; idx < 24 * 256; idx += NTH) {
        int row = idx >> 8;
        int kq  = idx & 255;
        int gg = row >> 3, cc = row & 7;
        const float* Wsel = (gg == 0) ? Wf : (gg == 1 ? Wo : Wc);
        float4 v = *(const float4*)(Wsel + (size_t)(c0col + cc) * KW + I_DIM + kq * 4);
        *(float4*)&ws[row * 1024 + kq * 4] = v;
    }
    for (int idx = tid; idx < B_DIM * CPB; idx += NTH) {
        int bb = idx >> 3, cc = idx & 7;
        csm[idx] = c0[bb * H_DIM + c0col + cc];
    }
    __syncthreads();

    const float* wbase = ws + rg * 8 * 1024 + kh * 512 + ks;
    const int c0i = ((2 * bg) ^ ks) << 2;         // swizzled chunk offsets (k&7==ks)
    const int c1i = ((2 * bg + 1) ^ ks) << 2;
    const int p   = ks + (kh << 3);               // partial index 0..15
    const bool wantTail = (out_size >= (B_DIM * S_DIM * H_DIM + 2 * B_DIM * H_DIM));

    for (int t = 0; t < S_DIM; t++) {
        const float* hsrc = g_hT[t & 1];
        float*       hdst = g_hT[(t + 1) & 1];

        // stage h with XOR swizzle: chunk c of row k -> position (c ^ (k&7))
        for (int idx = tid; idx < 8192; idx += NTH) {
            float4 v = __ldcg(((const float4*)hsrc) + idx);
            int kk = idx >> 3, cc = idx & 7;
            *(float4*)&hbuf[kk * 32 + ((cc ^ (kk & 7)) << 2)] = v;
        }
        __syncthreads();

        // dot: 8 rows x 8 batches per thread over 64 strided k's
        unsigned long long acc[8][4];
#pragma unroll
        for (int r = 0; r < 8; r++)
#pragma unroll
            for (int q2 = 0; q2 < 4; q2++) acc[r][q2] = 0ull;

        const float* hp0 = hbuf + (kh * 512 + ks) * 32;
#pragma unroll 4
        for (int j = 0; j < 64; j++) {
            const float* hrow = hp0 + j * 256;
            longlong2 ha = *(const longlong2*)(hrow + c0i);
            longlong2 hb = *(const longlong2*)(hrow + c1i);
            const float* wj = wbase + j * 8;
#pragma unroll
            for (int r = 0; r < 8; r++) {
                float w = wj[r * 1024];
                unsigned long long wd = pack2(w, w);
                acc[r][0] = ffma2(wd, (unsigned long long)ha.x, acc[r][0]);
                acc[r][1] = ffma2(wd, (unsigned long long)ha.y, acc[r][1]);
                acc[r][2] = ffma2(wd, (unsigned long long)hb.x, acc[r][2]);
                acc[r][3] = ffma2(wd, (unsigned long long)hb.y, acc[r][3]);
            }
        }
        __syncthreads();   // hbuf reads done before partials alias it

        // write partials: part[(row*32+b)*17 + p]
#pragma unroll
        for (int r = 0; r < 8; r++) {
            int row = rg * 8 + r;
#pragma unroll
            for (int q2 = 0; q2 < 4; q2++) {
                float2 v = unpack2(acc[r][q2]);
                int b0 = bg * 8 + q2 * 2;
                part[(row * 32 + b0) * 17 + p]       = v.x;
                part[(row * 32 + b0 + 1) * 17 + p]   = v.y;
            }
        }
        __syncthreads();

        // reduce 16 partials, add x-part, gate math, emit
        for (int idx = tid; idx < B_DIM * CPB; idx += NTH) {
            int bb = idx >> 3, cc = idx & 7;
            float pre[3];
#pragma unroll
            for (int gg = 0; gg < 3; gg++) {
                const float* pp = &part[((gg * 8 + cc) * 32 + bb) * 17];
                float s = 0.f;
#pragma unroll
                for (int u = 0; u < 16; u++) s += pp[u];
                pre[gg] = s + g_G[(((size_t)gg * S_DIM + t) * B_DIM + bb) * H_DIM
                                  + c0col + cc];
            }
            float f  = 1.f / (1.f + expf(-pre[0]));
            float o  = 1.f / (1.f + expf(-pre[1]));
            float ch = tanhf(pre[2]);
            float cold = csm[idx];
            float cn = f * cold + (1.f - f) * ch;
            float hn = o * tanhf(cn);
            csm[idx] = cn;
            int colg = c0col + cc;
            __stcg(&hdst[colg * B_DIM + bb], hn);
            out[((size_t)bb * S_DIM + t) * H_DIM + colg] = hn;
            if (t == S_DIM - 1 && wantTail) {
                size_t base = (size_t)B_DIM * S_DIM * H_DIM;
                out[base + (size_t)bb * H_DIM + colg] = hn;
                out[base + (size_t)B_DIM * H_DIM + (size_t)bb * H_DIM + colg] = cn;
            }
        }
        gridSync(nb);
    }
}

extern "C" void kernel_launch(void* const* d_in, const int* in_sizes, int n_in,
                              void* d_out, int out_size) {
    const float* x  = (const float*)d_in[0];
    const float* h0 = (const float*)d_in[1];
    const float* c0 = (const float*)d_in[2];
    const float* Wf = (const float*)d_in[3];
    const float* bf = (const float*)d_in[4];
    const float* Wo = (const float*)d_in[5];
    const float* bo = (const float*)d_in[6];
    const float* Wc = (const float*)d_in[7];
    const float* bc = (const float*)d_in[8];
    float* out = (float*)d_out;

    cudaFuncSetAttribute(lstm_recurrent,
                         cudaFuncAttributeMaxDynamicSharedMemorySize, SMEM_BYTES);

    dim3 gg(H_DIM / 128, (B_DIM * S_DIM) / 128, 3);
    lstm_gemm_x<<<gg, 256>>>(x, Wf, Wo, Wc, bf, bo, bc);
    lstm_init_h<<<(B_DIM * H_DIM + 255) / 256, 256>>>(h0);
    lstm_recurrent<<<NB_CTA, NTH, SMEM_BYTES>>>(Wf, Wo, Wc, c0, out, out_size);
}

// round 7
// speedup vs baseline: 1.6190x; 1.2702x over previous
#include <cuda_runtime.h>
#include <cstdint>

#define B_DIM 32
#define S_DIM 1024
#define H_DIM 1024
#define I_DIM 1024
#define KW    2048

__device__ float g_G[(size_t)3 * S_DIM * B_DIM * H_DIM]; // [g][t][b][h]
__device__ float g_hT[2][H_DIM * B_DIM];                 // h transposed [h][b]
__device__ unsigned g_barCount = 0;
__device__ unsigned g_barGen   = 0;

__device__ __forceinline__ unsigned long long pack2(float lo, float hi) {
    unsigned long long r;
    asm("mov.b64 %0, {%1, %2};" : "=l"(r)
        : "r"(__float_as_uint(lo)), "r"(__float_as_uint(hi)));
    return r;
}
__device__ __forceinline__ unsigned long long ffma2(unsigned long long a,
                                                    unsigned long long b,
                                                    unsigned long long c) {
    unsigned long long d;
    asm("fma.rn.f32x2 %0, %1, %2, %3;" : "=l"(d) : "l"(a), "l"(b), "l"(c));
    return d;
}
__device__ __forceinline__ float2 unpack2(unsigned long long v) {
    unsigned lo, hi;
    asm("mov.b64 {%0, %1}, %2;" : "=r"(lo), "=r"(hi) : "l"(v));
    float2 f; f.x = __uint_as_float(lo); f.y = __uint_as_float(hi);
    return f;
}

// ============ Phase 1: G = x @ W[:, :I]^T + b, 3 gates (unchanged) ============
__global__ __launch_bounds__(256, 2)
void lstm_gemm_x(const float* __restrict__ x,
                 const float* __restrict__ Wf, const float* __restrict__ Wo,
                 const float* __restrict__ Wc,
                 const float* __restrict__ bf, const float* __restrict__ bo,
                 const float* __restrict__ bc) {
    __shared__ float As[8][128];
    __shared__ float Bs[8][128];

    const int g = blockIdx.z;
    const float* W    = (g == 0) ? Wf : (g == 1 ? Wo : Wc);
    const float* bias = (g == 0) ? bf : (g == 1 ? bo : bc);

    const int rowBase = blockIdx.y * 128;
    const int colBase = blockIdx.x * 128;
    const int tid  = threadIdx.x;
    const int lr   = tid >> 1;
    const int lk   = (tid & 1) * 4;
    const int mIdx = tid >> 4;
    const int nIdx = tid & 15;

    const float* aPtr = x + (size_t)(rowBase + lr) * I_DIM + lk;
    const float* bPtr = W + (size_t)(colBase + lr) * KW    + lk;

    unsigned long long acc[8][4];
#pragma unroll
    for (int i = 0; i < 8; i++)
#pragma unroll
        for (int j = 0; j < 4; j++) acc[i][j] = 0ull;

    float4 av = *(const float4*)aPtr;
    float4 bv = *(const float4*)bPtr;

    for (int kt = 0; kt < 1024; kt += 8) {
        As[lk + 0][lr] = av.x; As[lk + 1][lr] = av.y;
        As[lk + 2][lr] = av.z; As[lk + 3][lr] = av.w;
        Bs[lk + 0][lr] = bv.x; Bs[lk + 1][lr] = bv.y;
        Bs[lk + 2][lr] = bv.z; Bs[lk + 3][lr] = bv.w;
        __syncthreads();

        if (kt + 8 < 1024) {
            av = *(const float4*)(aPtr + kt + 8);
            bv = *(const float4*)(bPtr + kt + 8);
        }

#pragma unroll
        for (int k = 0; k < 8; k++) {
            float4 a0 = *(const float4*)&As[k][mIdx * 4];
            float4 a1 = *(const float4*)&As[k][64 + mIdx * 4];
            longlong2 b0 = *(const longlong2*)&Bs[k][nIdx * 4];
            longlong2 b1 = *(const longlong2*)&Bs[k][64 + nIdx * 4];

            unsigned long long ad[8];
            ad[0] = pack2(a0.x, a0.x); ad[1] = pack2(a0.y, a0.y);
            ad[2] = pack2(a0.z, a0.z); ad[3] = pack2(a0.w, a0.w);
            ad[4] = pack2(a1.x, a1.x); ad[5] = pack2(a1.y, a1.y);
            ad[6] = pack2(a1.z, a1.z); ad[7] = pack2(a1.w, a1.w);

            unsigned long long bp0 = (unsigned long long)b0.x;
            unsigned long long bp1 = (unsigned long long)b0.y;
            unsigned long long bp2 = (unsigned long long)b1.x;
            unsigned long long bp3 = (unsigned long long)b1.y;
#pragma unroll
            for (int i = 0; i < 8; i++) {
                acc[i][0] = ffma2(ad[i], bp0, acc[i][0]);
                acc[i][1] = ffma2(ad[i], bp1, acc[i][1]);
                acc[i][2] = ffma2(ad[i], bp2, acc[i][2]);
                acc[i][3] = ffma2(ad[i], bp3, acc[i][3]);
            }
        }
        __syncthreads();
    }

#pragma unroll
    for (int i = 0; i < 8; i++) {
        int r  = rowBase + ((i < 4) ? (mIdx * 4 + i) : (64 + mIdx * 4 + (i - 4)));
        int bb = r >> 10;
        int ss = r & 1023;
        float* orow = g_G + (((size_t)g * S_DIM + ss) * B_DIM + bb) * H_DIM;
#pragma unroll
        for (int p = 0; p < 4; p++) {
            int cc = colBase + ((p < 2) ? (nIdx * 4 + p * 2)
                                        : (64 + nIdx * 4 + (p - 2) * 2));
            float2 v = unpack2(acc[i][p]);
            v.x += bias[cc];
            v.y += bias[cc + 1];
            *(float2*)&orow[cc] = v;
        }
    }
}

// ============ init h0 (transposed) ============
__global__ void lstm_init_h(const float* __restrict__ h0) {
    int idx = blockIdx.x * blockDim.x + threadIdx.x;
    if (idx < B_DIM * H_DIM) {
        int b = idx >> 10, h = idx & 1023;
        g_hT[0][h * B_DIM + b] = h0[idx];
    }
}

// ============ Phase 2: persistent recurrence ============
#define NB_CTA 128
#define CPB    8
#define NTH    384
// smem: ws 24*1024 | region2 = max(hbuf 32768, part 32*801) | csm 256
#define SMEM_FLOATS (24 * 1024 + 32768 + 256)
#define SMEM_BYTES (SMEM_FLOATS * 4)

__device__ __forceinline__ void gridSync(unsigned nb) {
    __syncthreads();
    if (threadIdx.x == 0) {
        __threadfence();
        unsigned gen = *(volatile unsigned*)&g_barGen;
        if (atomicAdd(&g_barCount, 1u) == nb - 1u) {
            *(volatile unsigned*)&g_barCount = 0u;
            __threadfence();
            *(volatile unsigned*)&g_barGen = gen + 1u;
        } else {
            while (*(volatile unsigned*)&g_barGen == gen) { __nanosleep(20); }
        }
        __threadfence();
    }
    __syncthreads();
}

__device__ __forceinline__ float sigm_f(float x) {
    return __fdividef(1.f, 1.f + __expf(-x));
}
__device__ __forceinline__ float tanh_f(float x) {
    return 1.f - __fdividef(2.f, 1.f + __expf(2.f * x));
}

extern __shared__ float s_mem[];

__global__ __launch_bounds__(NTH, 1)
void lstm_recurrent(const float* __restrict__ Wf, const float* __restrict__ Wo,
                    const float* __restrict__ Wc, const float* __restrict__ c0,
                    float* __restrict__ out, int out_size) {
    float* ws   = s_mem;                       // 24 rows x 1024
    float* hbuf = s_mem + 24 * 1024;           // staged h, XOR-swizzled chunks
    float* csm  = s_mem + 24 * 1024 + 32768;   // cell state [cc][bb]
    float* part = hbuf;                        // alias: [b]*801 + [p]*25 + gcol

    const int tid   = threadIdx.x;
    const int c0col = blockIdx.x * CPB;
    const int lane  = tid & 31;
    const int warp  = tid >> 5;          // 12 warps
    const int ks    = lane & 7;          // k-lane
    const int bg    = lane >> 3;         // batch-group (8 batches each)
    const int rg    = warp % 3;          // gate
    const int kh    = warp / 3;          // K-quarter (0..3)
    const unsigned nb = gridDim.x;

    // recurrent weights -> smem: ws[g*8+c][k] = Wg[c0col+c][I+k]
    for (int idx = tid; idx < 24 * 256; idx += NTH) {
        int row = idx >> 8;
        int kq  = idx & 255;
        int gg = row >> 3, cc = row & 7;
        const float* Wsel = (gg == 0) ? Wf : (gg == 1 ? Wo : Wc);
        float4 v = *(const float4*)(Wsel + (size_t)(c0col + cc) * KW + I_DIM + kq * 4);
        *(float4*)&ws[row * 1024 + kq * 4] = v;
    }
    // cell state: csm[cc*32 + bb]
    for (int idx = tid; idx < B_DIM * CPB; idx += NTH) {
        int cc = idx >> 5, bb = idx & 31;
        csm[cc * 32 + bb] = c0[bb * H_DIM + c0col + cc];
    }
    __syncthreads();

    const float* wbase = ws + rg * 8 * 1024 + kh * 256 + ks;
    const int c0i = ((2 * bg) ^ ks) << 2;
    const int c1i = ((2 * bg + 1) ^ ks) << 2;
    const int p   = kh * 8 + ks;              // 0..31 k-slice id
    const bool wantTail = (out_size >= (B_DIM * S_DIM * H_DIM + 2 * B_DIM * H_DIM));

    for (int t = 0; t < S_DIM; t++) {
        const float* hsrc = g_hT[t & 1];
        float*       hdst = g_hT[(t + 1) & 1];

        // prefetch x-part pre-activations (DRAM) for this CTA's cells
        float gxr0 = 0.f, gxr1 = 0.f, gxr2 = 0.f;
        if (warp < 8) {
            size_t ofs = ((size_t)t * B_DIM + lane) * H_DIM + c0col + warp;
            gxr0 = __ldg(&g_G[ofs]);
            gxr1 = __ldg(&g_G[(size_t)S_DIM * B_DIM * H_DIM + ofs]);
            gxr2 = __ldg(&g_G[2 * (size_t)S_DIM * B_DIM * H_DIM + ofs]);
        }

        // stage h with XOR swizzle: chunk c of row k -> position (c ^ (k&7))
        for (int idx = tid; idx < 8192; idx += NTH) {
            float4 v = __ldcg(((const float4*)hsrc) + idx);
            int kk = idx >> 3, cc = idx & 7;
            *(float4*)&hbuf[kk * 32 + ((cc ^ (kk & 7)) << 2)] = v;
        }
        __syncthreads();

        // dot: 8 rows x 8 batches per thread over 32 strided k's (K-quarter kh)
        unsigned long long acc[8][4];
#pragma unroll
        for (int r = 0; r < 8; r++)
#pragma unroll
            for (int q2 = 0; q2 < 4; q2++) acc[r][q2] = 0ull;

        const float* hp0 = hbuf + (kh * 256 + ks) * 32;
#pragma unroll 4
        for (int j = 0; j < 32; j++) {
            const float* hrow = hp0 + j * 256;
            longlong2 ha = *(const longlong2*)(hrow + c0i);
            longlong2 hb = *(const longlong2*)(hrow + c1i);
            const float* wj = wbase + j * 8;
#pragma unroll
            for (int r = 0; r < 8; r++) {
                float w = wj[r * 1024];
                unsigned long long wd = pack2(w, w);
                acc[r][0] = ffma2(wd, (unsigned long long)ha.x, acc[r][0]);
                acc[r][1] = ffma2(wd, (unsigned long long)ha.y, acc[r][1]);
                acc[r][2] = ffma2(wd, (unsigned long long)hb.x, acc[r][2]);
                acc[r][3] = ffma2(wd, (unsigned long long)hb.y, acc[r][3]);
            }
        }
        __syncthreads();   // hbuf reads done before partials alias it

        // write partials: part[b*801 + p*25 + gcol]  (conflict-free)
#pragma unroll
        for (int r = 0; r < 8; r++) {
            int gcol = rg * 8 + r;
#pragma unroll
            for (int q2 = 0; q2 < 4; q2++) {
                float2 v = unpack2(acc[r][q2]);
                int b0 = bg * 8 + q2 * 2;
                part[b0 * 801 + p * 25 + gcol]       = v.x;
                part[(b0 + 1) * 801 + p * 25 + gcol] = v.y;
            }
        }
        __syncthreads();

        // reduce 32 partials + gate math: warp -> cc, lane -> bb (conflict-free)
        if (warp < 8) {
            const int cc = warp, bb = lane;
            const float* pb = &part[bb * 801];
            float s0a = 0.f, s0b = 0.f, s1a = 0.f, s1b = 0.f, s2a = 0.f, s2b = 0.f;
#pragma unroll
            for (int u = 0; u < 32; u += 2) {
                s0a += pb[u * 25 + cc];
                s0b += pb[(u + 1) * 25 + cc];
                s1a += pb[u * 25 + 8 + cc];
                s1b += pb[(u + 1) * 25 + 8 + cc];
                s2a += pb[u * 25 + 16 + cc];
                s2b += pb[(u + 1) * 25 + 16 + cc];
            }
            float pre0 = s0a + s0b + gxr0;
            float pre1 = s1a + s1b + gxr1;
            float pre2 = s2a + s2b + gxr2;

            float f  = sigm_f(pre0);
            float o  = sigm_f(pre1);
            float ch = tanh_f(pre2);
            float cold = csm[cc * 32 + bb];
            float cn = f * (cold - ch) + ch;
            float hn = o * tanh_f(cn);
            csm[cc * 32 + bb] = cn;

            int colg = c0col + cc;
            __stcg(&hdst[colg * B_DIM + bb], hn);
            out[((size_t)bb * S_DIM + t) * H_DIM + colg] = hn;
            if (t == S_DIM - 1 && wantTail) {
                size_t base = (size_t)B_DIM * S_DIM * H_DIM;
                out[base + (size_t)bb * H_DIM + colg] = hn;
                out[base + (size_t)B_DIM * H_DIM + (size_t)bb * H_DIM + colg] = cn;
            }
        }
        gridSync(nb);
    }
}

extern "C" void kernel_launch(void* const* d_in, const int* in_sizes, int n_in,
                              void* d_out, int out_size) {
    const float* x  = (const float*)d_in[0];
    const float* h0 = (const float*)d_in[1];
    const float* c0 = (const float*)d_in[2];
    const float* Wf = (const float*)d_in[3];
    const float* bf = (const float*)d_in[4];
    const float* Wo = (const float*)d_in[5];
    const float* bo = (const float*)d_in[6];
    const float* Wc = (const float*)d_in[7];
    const float* bc = (const float*)d_in[8];
    float* out = (float*)d_out;

    cudaFuncSetAttribute(lstm_recurrent,
                         cudaFuncAttributeMaxDynamicSharedMemorySize, SMEM_BYTES);

    dim3 gg(H_DIM / 128, (B_DIM * S_DIM) / 128, 3);
    lstm_gemm_x<<<gg, 256>>>(x, Wf, Wo, Wc, bf, bo, bc);
    lstm_init_h<<<(B_DIM * H_DIM + 255) / 256, 256>>>(h0);
    lstm_recurrent<<<NB_CTA, NTH, SMEM_BYTES>>>(Wf, Wo, Wc, c0, out, out_size);
}

// round 9
// speedup vs baseline: 1.9457x; 1.2018x over previous
#include <cuda_runtime.h>
#include <cuda_bf16.h>
#include <cstdint>

#define B_DIM 32
#define S_DIM 1024
#define H_DIM 1024
#define I_DIM 1024
#define KW    2048

// ---------------- scratch ----------------
__device__ float g_G[(size_t)3 * S_DIM * B_DIM * H_DIM];   // [g][t][b][h]
__device__ float g_hT[2][H_DIM * B_DIM];                   // h transposed [h][b]
__device__ unsigned g_barCount = 0;
__device__ unsigned g_barGen   = 0;
__device__ __nv_bfloat16 g_xhi[(size_t)B_DIM * S_DIM * I_DIM];
__device__ __nv_bfloat16 g_xlo[(size_t)B_DIM * S_DIM * I_DIM];
__device__ __nv_bfloat16 g_whi[(size_t)3 * H_DIM * I_DIM]; // rows g*1024+h, k<1024
__device__ __nv_bfloat16 g_wlo[(size_t)3 * H_DIM * I_DIM];

// ---------------- helpers ----------------
__device__ __forceinline__ unsigned long long pack2(float lo, float hi) {
    unsigned long long r;
    asm("mov.b64 %0, {%1, %2};" : "=l"(r)
        : "r"(__float_as_uint(lo)), "r"(__float_as_uint(hi)));
    return r;
}
__device__ __forceinline__ unsigned long long ffma2(unsigned long long a,
                                                    unsigned long long b,
                                                    unsigned long long c) {
    unsigned long long d;
    asm("fma.rn.f32x2 %0, %1, %2, %3;" : "=l"(d) : "l"(a), "l"(b), "l"(c));
    return d;
}
__device__ __forceinline__ float2 unpack2(unsigned long long v) {
    unsigned lo, hi;
    asm("mov.b64 {%0, %1}, %2;" : "=r"(lo), "=r"(hi) : "l"(v));
    float2 f; f.x = __uint_as_float(lo); f.y = __uint_as_float(hi);
    return f;
}
__device__ __forceinline__ uint32_t smem_u32(const void* p) {
    uint32_t a;
    asm("{ .reg .u64 t; cvta.to.shared.u64 t, %1; cvt.u32.u64 %0, t; }"
        : "=r"(a) : "l"(p));
    return a;
}
__device__ __forceinline__ void cpasync16(uint32_t s, const void* g) {
    asm volatile("cp.async.cg.shared.global [%0], [%1], 16;" :: "r"(s), "l"(g));
}
#define CP_COMMIT() asm volatile("cp.async.commit_group;" ::: "memory")
#define CP_WAIT1()  asm volatile("cp.async.wait_group 1;" ::: "memory")

__device__ __forceinline__ void ldsm_x4(uint32_t& r0, uint32_t& r1,
                                        uint32_t& r2, uint32_t& r3,
                                        uint32_t addr) {
    asm volatile("ldmatrix.sync.aligned.m8n8.x4.shared.b16 {%0,%1,%2,%3}, [%4];"
                 : "=r"(r0), "=r"(r1), "=r"(r2), "=r"(r3) : "r"(addr));
}
__device__ __forceinline__ void mma16816(float* d, const uint32_t* a,
                                         uint32_t b0, uint32_t b1) {
    asm volatile("mma.sync.aligned.m16n8k16.row.col.f32.bf16.bf16.f32 "
                 "{%0,%1,%2,%3}, {%4,%5,%6,%7}, {%8,%9}, {%0,%1,%2,%3};"
                 : "+f"(d[0]), "+f"(d[1]), "+f"(d[2]), "+f"(d[3])
                 : "r"(a[0]), "r"(a[1]), "r"(a[2]), "r"(a[3]),
                   "r"(b0), "r"(b1));
}

// ---------------- conversion kernels ----------------
__global__ void cvt_x(const float* __restrict__ x) {
    size_t i = (size_t)blockIdx.x * blockDim.x + threadIdx.x;
    if (i < (size_t)B_DIM * S_DIM * I_DIM) {
        float v = x[i];
        __nv_bfloat16 h = __float2bfloat16(v);
        g_xhi[i] = h;
        g_xlo[i] = __float2bfloat16(v - __bfloat162float(h));
    }
}
__global__ void cvt_w(const float* __restrict__ Wf, const float* __restrict__ Wo,
                      const float* __restrict__ Wc) {
    size_t i = (size_t)blockIdx.x * blockDim.x + threadIdx.x;
    if (i < (size_t)3 * H_DIM * I_DIM) {
        int g = (int)(i / (H_DIM * I_DIM));
        size_t rem = i - (size_t)g * H_DIM * I_DIM;
        int h = (int)(rem >> 10), k = (int)(rem & 1023);
        const float* W = (g == 0) ? Wf : (g == 1 ? Wo : Wc);
        float v = W[(size_t)h * KW + k];
        __nv_bfloat16 hh = __float2bfloat16(v);
        g_whi[i] = hh;
        g_wlo[i] = __float2bfloat16(v - __bfloat162float(hh));
    }
}

// ---------------- Phase 1: mma.sync bf16 GEMM (3-term hi/lo) ----------------
// CTA tile 128x128, K in 32 chunks of 32 (2 k16 each), 2-stage cp.async.
#define APAD 40                  // bf16 elems per smem row (80B, 16B-aligned)
#define ALO_OFF 5120             // elem offsets within a stage
#define BHI_OFF 10240
#define BLO_OFF 15360
#define STG_ELEMS 20480          // 40960 B per stage
#define GSMEM_BYTES (2 * STG_ELEMS * 2)

extern __shared__ __nv_bfloat16 g_sm[];

__global__ __launch_bounds__(256, 1)
void mma_gemm(const float* __restrict__ bf, const float* __restrict__ bo,
              const float* __restrict__ bc) {
    uint32_t sbase = smem_u32(g_sm);
    const int tid = threadIdx.x, lane = tid & 31, warp = tid >> 5;
    const int wm = warp & 1, wn = warp >> 1;          // warp grid 2(m) x 4(n)
    const int g  = blockIdx.x >> 3;
    const int h0 = (blockIdx.x & 7) * 128;
    const int rowBase = blockIdx.y * 128;             // rows = b*1024+s
    const size_t aG = (size_t)rowBase * 1024;
    const size_t bG = ((size_t)g * 1024 + h0) * 1024;

    auto loadStage = [&](int st, int kt) {
        uint32_t sb = sbase + st * (STG_ELEMS * 2);
        for (int i = tid; i < 512; i += 256) {
            int r = i >> 2, c = i & 3;
            uint32_t off = (uint32_t)(r * APAD + c * 8) * 2;
            size_t src = (size_t)r * 1024 + kt + c * 8;
            cpasync16(sb + off,               g_xhi + aG + src);
            cpasync16(sb + ALO_OFF * 2 + off, g_xlo + aG + src);
            cpasync16(sb + BHI_OFF * 2 + off, g_whi + bG + src);
            cpasync16(sb + BLO_OFF * 2 + off, g_wlo + bG + src);
        }
    };

    float acc[4][4][4];
#pragma unroll
    for (int mi = 0; mi < 4; mi++)
#pragma unroll
        for (int ni = 0; ni < 4; ni++)
#pragma unroll
            for (int u = 0; u < 4; u++) acc[mi][ni][u] = 0.f;

    loadStage(0, 0);  CP_COMMIT();
    loadStage(1, 32); CP_COMMIT();

    // ldmatrix lane addressing
    const int aRow = wm * 64 + (lane & 15);           // + mi*16
    const int aColB = (lane >> 4) * 16;               // + kk*32 (bytes)
    const int bRow = wn * 32 + (lane & 7) + ((lane >> 4) << 3);  // + nh*16
    const int bColB = ((lane >> 3) & 1) * 16;         // + kk*32 (bytes)

    for (int kt = 0; kt < 32; kt++) {
        CP_WAIT1();
        __syncthreads();
        uint32_t sb = sbase + (kt & 1) * (STG_ELEMS * 2);
#pragma unroll
        for (int kk = 0; kk < 2; kk++) {
            uint32_t ahi[4][4], alo[4][4];
#pragma unroll
            for (int mi = 0; mi < 4; mi++) {
                uint32_t ad = sb + (uint32_t)((aRow + mi * 16) * APAD) * 2
                            + kk * 32 + aColB;
                ldsm_x4(ahi[mi][0], ahi[mi][1], ahi[mi][2], ahi[mi][3], ad);
                ldsm_x4(alo[mi][0], alo[mi][1], alo[mi][2], alo[mi][3],
                        ad + ALO_OFF * 2);
            }
            uint32_t bhi[4][2], blo[4][2];
#pragma unroll
            for (int nh = 0; nh < 2; nh++) {
                uint32_t bd = sb + BHI_OFF * 2
                            + (uint32_t)((bRow + nh * 16) * APAD) * 2
                            + kk * 32 + bColB;
                uint32_t r0, r1, r2, r3;
                ldsm_x4(r0, r1, r2, r3, bd);
                bhi[nh * 2][0] = r0; bhi[nh * 2][1] = r1;
                bhi[nh * 2 + 1][0] = r2; bhi[nh * 2 + 1][1] = r3;
                ldsm_x4(r0, r1, r2, r3, bd + (BLO_OFF - BHI_OFF) * 2);
                blo[nh * 2][0] = r0; blo[nh * 2][1] = r1;
                blo[nh * 2 + 1][0] = r2; blo[nh * 2 + 1][1] = r3;
            }
#pragma unroll
            for (int mi = 0; mi < 4; mi++)
#pragma unroll
                for (int ni = 0; ni < 4; ni++) {
                    mma16816(acc[mi][ni], ahi[mi], bhi[ni][0], bhi[ni][1]);
                    mma16816(acc[mi][ni], ahi[mi], blo[ni][0], blo[ni][1]);
                    mma16816(acc[mi][ni], alo[mi], bhi[ni][0], bhi[ni][1]);
                }
        }
        __syncthreads();
        if (kt + 2 < 32) loadStage(kt & 1, (kt + 2) * 32);
        CP_COMMIT();
    }

    // epilogue -> g_G[g][t][b][h]
    const float* bias = (g == 0) ? bf : (g == 1 ? bo : bc);
    const int b    = rowBase >> 10;
    const int tLoc = rowBase & 1023;
#pragma unroll
    for (int ni = 0; ni < 4; ni++) {
        int h = h0 + wn * 32 + ni * 8 + (lane & 3) * 2;
        float bx = __ldg(&bias[h]), by = __ldg(&bias[h + 1]);
#pragma unroll
        for (int mi = 0; mi < 4; mi++) {
            int t0 = tLoc + wm * 64 + mi * 16 + (lane >> 2);
            float2 v0 = make_float2(acc[mi][ni][0] + bx, acc[mi][ni][1] + by);
            float2 v1 = make_float2(acc[mi][ni][2] + bx, acc[mi][ni][3] + by);
            *(float2*)&g_G[(((size_t)g * S_DIM + t0) * B_DIM + b) * H_DIM + h] = v0;
            *(float2*)&g_G[(((size_t)g * S_DIM + t0 + 8) * B_DIM + b) * H_DIM + h] = v1;
        }
    }
}

// ---------------- init h0 (transposed) ----------------
__global__ void lstm_init_h(const float* __restrict__ h0) {
    int idx = blockIdx.x * blockDim.x + threadIdx.x;
    if (idx < B_DIM * H_DIM) {
        int b = idx >> 10, h = idx & 1023;
        g_hT[0][h * B_DIM + b] = h0[idx];
    }
}

// ---------------- Phase 2: persistent recurrence ----------------
#define NB_CTA 128
#define CPB    8
#define NTH    384
#define SMEM_FLOATS (24 * 1024 + 32768 + 256)
#define SMEM_BYTES (SMEM_FLOATS * 4)

__device__ __forceinline__ void gridSync(unsigned nb) {
    __syncthreads();
    if (threadIdx.x == 0) {
        __threadfence();
        unsigned gen = *(volatile unsigned*)&g_barGen;
        if (atomicAdd(&g_barCount, 1u) == nb - 1u) {
            *(volatile unsigned*)&g_barCount = 0u;
            __threadfence();
            *(volatile unsigned*)&g_barGen = gen + 1u;
        } else {
            while (*(volatile unsigned*)&g_barGen == gen) { __nanosleep(20); }
        }
        __threadfence();
    }
    __syncthreads();
}
__device__ __forceinline__ float sigm_f(float x) {
    return __fdividef(1.f, 1.f + __expf(-x));
}
__device__ __forceinline__ float tanh_f(float x) {
    return 1.f - __fdividef(2.f, 1.f + __expf(2.f * x));
}

extern __shared__ float s_mem[];

__global__ __launch_bounds__(NTH, 1)
void lstm_recurrent(const float* __restrict__ Wf, const float* __restrict__ Wo,
                    const float* __restrict__ Wc, const float* __restrict__ c0,
                    float* __restrict__ out, int out_size) {
    float* ws   = s_mem;
    float* hbuf = s_mem + 24 * 1024;
    float* csm  = s_mem + 24 * 1024 + 32768;
    float* part = hbuf;                        // alias: [b]*801 + [p]*25 + gcol

    const int tid   = threadIdx.x;
    const int c0col = blockIdx.x * CPB;
    const int lane  = tid & 31;
    const int warp  = tid >> 5;
    const int ks    = lane & 7;
    const int bg    = lane >> 3;
    const int rg    = warp % 3;
    const int kh    = warp / 3;
    const unsigned nb = gridDim.x;

    for (int idx = tid; idx < 24 * 256; idx += NTH) {
        int row = idx >> 8;
        int kq  = idx & 255;
        int gg = row >> 3, cc = row & 7;
        const float* Wsel = (gg == 0) ? Wf : (gg == 1 ? Wo : Wc);
        float4 v = *(const float4*)(Wsel + (size_t)(c0col + cc) * KW + I_DIM + kq * 4);
        *(float4*)&ws[row * 1024 + kq * 4] = v;
    }
    for (int idx = tid; idx < B_DIM * CPB; idx += NTH) {
        int cc = idx >> 5, bb = idx & 31;
        csm[cc * 32 + bb] = c0[bb * H_DIM + c0col + cc];
    }
    __syncthreads();

    const float* wrowBase = ws + rg * 8 * 1024 + kh * 256 + ks * 4;
    const float* hBase    = hbuf + (kh * 256 + ks * 4) * 32;
    const int c0i = ((2 * bg) ^ ks) << 2;
    const int c1i = ((2 * bg + 1) ^ ks) << 2;
    const int p   = kh * 8 + ks;
    const bool wantTail = (out_size >= (B_DIM * S_DIM * H_DIM + 2 * B_DIM * H_DIM));

    for (int t = 0; t < S_DIM; t++) {
        const float* hsrc = g_hT[t & 1];
        float*       hdst = g_hT[(t + 1) & 1];

        // prefetch x-part (hidden under staging + dot)
        float gxr0 = 0.f, gxr1 = 0.f, gxr2 = 0.f;
        if (warp < 8) {
            size_t ofs = ((size_t)t * B_DIM + lane) * H_DIM + c0col + warp;
            const size_t GSTR = (size_t)S_DIM * B_DIM * H_DIM;
            gxr0 = __ldg(&g_G[ofs]);
            gxr1 = __ldg(&g_G[GSTR + ofs]);
            gxr2 = __ldg(&g_G[2 * GSTR + ofs]);
        }

        // stage h; swizzle now keyed on (k>>2)&7 so 4 consecutive k share a key
        for (int idx = tid; idx < 8192; idx += NTH) {
            float4 v = __ldcg(((const float4*)hsrc) + idx);
            int kk = idx >> 3, cc = idx & 7;
            *(float4*)&hbuf[kk * 32 + ((cc ^ ((kk >> 2) & 7)) << 2)] = v;
        }
        __syncthreads();

        // dot: 8 rows x 8 batches, 4 consecutive k per slice, 8 j-iters
        unsigned long long acc[8][4];
#pragma unroll
        for (int r = 0; r < 8; r++)
#pragma unroll
            for (int q2 = 0; q2 < 4; q2++) acc[r][q2] = 0ull;

#pragma unroll
        for (int j = 0; j < 8; j++) {
            float4 wv[8];
#pragma unroll
            for (int r = 0; r < 8; r++)
                wv[r] = *(const float4*)(wrowBase + r * 1024 + j * 32);
            const float* hrow0 = hBase + j * 32 * 32;
#pragma unroll
            for (int dk = 0; dk < 4; dk++) {
                const float* hrow = hrow0 + dk * 32;
                longlong2 ha = *(const longlong2*)(hrow + c0i);
                longlong2 hb = *(const longlong2*)(hrow + c1i);
#pragma unroll
                for (int r = 0; r < 8; r++) {
                    float w = (dk == 0) ? wv[r].x : (dk == 1) ? wv[r].y
                            : (dk == 2) ? wv[r].z : wv[r].w;
                    unsigned long long wd = pack2(w, w);
                    acc[r][0] = ffma2(wd, (unsigned long long)ha.x, acc[r][0]);
                    acc[r][1] = ffma2(wd, (unsigned long long)ha.y, acc[r][1]);
                    acc[r][2] = ffma2(wd, (unsigned long long)hb.x, acc[r][2]);
                    acc[r][3] = ffma2(wd, (unsigned long long)hb.y, acc[r][3]);
                }
            }
        }
        __syncthreads();

#pragma unroll
        for (int r = 0; r < 8; r++) {
            int gcol = rg * 8 + r;
#pragma unroll
            for (int q2 = 0; q2 < 4; q2++) {
                float2 v = unpack2(acc[r][q2]);
                int b0 = bg * 8 + q2 * 2;
                part[b0 * 801 + p * 25 + gcol]       = v.x;
                part[(b0 + 1) * 801 + p * 25 + gcol] = v.y;
            }
        }
        __syncthreads();

        if (warp < 8) {
            const int cc = warp, bb = lane;
            const float* pb = &part[bb * 801];
            float s0a = 0.f, s0b = 0.f, s1a = 0.f, s1b = 0.f, s2a = 0.f, s2b = 0.f;
#pragma unroll
            for (int u = 0; u < 32; u += 2) {
                s0a += pb[u * 25 + cc];
                s0b += pb[(u + 1) * 25 + cc];
                s1a += pb[u * 25 + 8 + cc];
                s1b += pb[(u + 1) * 25 + 8 + cc];
                s2a += pb[u * 25 + 16 + cc];
                s2b += pb[(u + 1) * 25 + 16 + cc];
            }
            float pre0 = s0a + s0b + gxr0;
            float pre1 = s1a + s1b + gxr1;
            float pre2 = s2a + s2b + gxr2;

            float f  = sigm_f(pre0);
            float o  = sigm_f(pre1);
            float ch = tanh_f(pre2);
            float cold = csm[cc * 32 + bb];
            float cn = f * (cold - ch) + ch;
            float hn = o * tanh_f(cn);
            csm[cc * 32 + bb] = cn;

            int colg = c0col + cc;
            __stcg(&hdst[colg * B_DIM + bb], hn);
            out[((size_t)bb * S_DIM + t) * H_DIM + colg] = hn;
            if (t == S_DIM - 1 && wantTail) {
                size_t base = (size_t)B_DIM * S_DIM * H_DIM;
                out[base + (size_t)bb * H_DIM + colg] = hn;
                out[base + (size_t)B_DIM * H_DIM + (size_t)bb * H_DIM + colg] = cn;
            }
        }
        gridSync(nb);
    }
}

// ---------------- launch ----------------
extern "C" void kernel_launch(void* const* d_in, const int* in_sizes, int n_in,
                              void* d_out, int out_size) {
    const float* x  = (const float*)d_in[0];
    const float* h0 = (const float*)d_in[1];
    const float* c0 = (const float*)d_in[2];
    const float* Wf = (const float*)d_in[3];
    const float* bf = (const float*)d_in[4];
    const float* Wo = (const float*)d_in[5];
    const float* bo = (const float*)d_in[6];
    const float* Wc = (const float*)d_in[7];
    const float* bc = (const float*)d_in[8];
    float* out = (float*)d_out;

    cudaFuncSetAttribute(mma_gemm,
                         cudaFuncAttributeMaxDynamicSharedMemorySize, GSMEM_BYTES);
    cudaFuncSetAttribute(lstm_recurrent,
                         cudaFuncAttributeMaxDynamicSharedMemorySize, SMEM_BYTES);

    cvt_x<<<(B_DIM * S_DIM * I_DIM + 255) / 256, 256>>>(x);
    cvt_w<<<(3 * H_DIM * I_DIM + 255) / 256, 256>>>(Wf, Wo, Wc);
    mma_gemm<<<dim3(24, 256), 256, GSMEM_BYTES>>>(bf, bo, bc);
    lstm_init_h<<<(B_DIM * H_DIM + 255) / 256, 256>>>(h0);
    lstm_recurrent<<<NB_CTA, NTH, SMEM_BYTES>>>(Wf, Wo, Wc, c0, out, out_size);
}